// round 1
// baseline (speedup 1.0000x reference)
#include <cuda_runtime.h>
#include <cstddef>

#define BB   32
#define NN   1024
#define DIMV 512
#define HH   8
#define KDV  64
#define DV   256
#define DHV  2048
#define QKVV 3072
__device__ const float SCALE = 0.125f;

// ---------------- scratch (device globals; allocation-free) ----------------
__device__ float g_xn[(size_t)BB * NN * DIMV];     //  64 MB
__device__ float g_qkv[(size_t)BB * NN * QKVV];    // 384 MB
__device__ float g_attn[(size_t)BB * HH * NN * NN];// 1 GB  (bz=b*H+h, q, k)
__device__ float g_av[(size_t)BB * NN * DHV];      // 256 MB (b, q, h, d)

// ---------------- LayerNorm: one block per token row ----------------
__global__ void __launch_bounds__(128)
ln_kernel(const float* __restrict__ x, const float* __restrict__ gamma,
          const float* __restrict__ beta) {
    const int row = blockIdx.x;
    const int t = threadIdx.x;                       // 128 threads, 4 floats each
    const float4 v = reinterpret_cast<const float4*>(x)[(size_t)row * (DIMV / 4) + t];
    float s  = v.x + v.y + v.z + v.w;
    float sq = v.x * v.x + v.y * v.y + v.z * v.z + v.w * v.w;
    #pragma unroll
    for (int o = 16; o > 0; o >>= 1) {
        s  += __shfl_xor_sync(0xffffffffu, s, o);
        sq += __shfl_xor_sync(0xffffffffu, sq, o);
    }
    __shared__ float ss[4], ssq[4];
    const int w = t >> 5, l = t & 31;
    if (l == 0) { ss[w] = s; ssq[w] = sq; }
    __syncthreads();
    if (t == 0) {
        float S  = ss[0] + ss[1] + ss[2] + ss[3];
        float SQ = ssq[0] + ssq[1] + ssq[2] + ssq[3];
        float mu = S * (1.0f / DIMV);
        float var = SQ * (1.0f / DIMV) - mu * mu;
        ss[0]  = mu;
        ssq[0] = rsqrtf(var + 1e-5f);
    }
    __syncthreads();
    const float mu = ss[0], rstd = ssq[0];
    const float4 g  = reinterpret_cast<const float4*>(gamma)[t];
    const float4 bt = reinterpret_cast<const float4*>(beta)[t];
    float4 o;
    o.x = (v.x - mu) * rstd * g.x + bt.x;
    o.y = (v.y - mu) * rstd * g.y + bt.y;
    o.z = (v.z - mu) * rstd * g.z + bt.z;
    o.w = (v.w - mu) * rstd * g.w + bt.w;
    reinterpret_cast<float4*>(g_xn)[(size_t)row * (DIMV / 4) + t] = o;
}

// ---------------- generic row-major SGEMM + bias (qkv + proj) ----------------
// C[M,N] = A[M,K] @ B[K,N] + bias[N];  BM=128,BN=128,BK=16,TM=8,TN=8, 256 thr
__global__ void __launch_bounds__(256)
sgemm_bias(const float* __restrict__ A, const float* __restrict__ Bw,
           const float* __restrict__ bias, float* __restrict__ C,
           int M, int N, int K) {
    __shared__ float As[16][128];
    __shared__ float Bs[16][128];
    const int tid = threadIdx.x;
    const int m0 = blockIdx.y * 128;
    const int n0 = blockIdx.x * 128;
    const int tcol = tid & 15;     // 0..15 -> N
    const int trow = tid >> 4;     // 0..15 -> M
    float acc[8][8] = {};
    for (int kt = 0; kt < K; kt += 16) {
        #pragma unroll
        for (int i = 0; i < 2; ++i) {                 // A: 128x16 -> transposed
            int idx = tid + i * 256;
            int m = idx >> 2;
            int c = idx & 3;
            float4 v = *reinterpret_cast<const float4*>(
                &A[(size_t)(m0 + m) * K + kt + c * 4]);
            As[c * 4 + 0][m] = v.x; As[c * 4 + 1][m] = v.y;
            As[c * 4 + 2][m] = v.z; As[c * 4 + 3][m] = v.w;
        }
        #pragma unroll
        for (int i = 0; i < 2; ++i) {                 // B: 16x128 direct
            int idx = tid + i * 256;
            int r = idx >> 5;
            int c = idx & 31;
            *reinterpret_cast<float4*>(&Bs[r][c * 4]) =
                *reinterpret_cast<const float4*>(
                    &Bw[(size_t)(kt + r) * N + n0 + c * 4]);
        }
        __syncthreads();
        #pragma unroll
        for (int kk = 0; kk < 16; ++kk) {
            float a[8], b[8];
            *reinterpret_cast<float4*>(&a[0]) = *reinterpret_cast<const float4*>(&As[kk][trow * 8]);
            *reinterpret_cast<float4*>(&a[4]) = *reinterpret_cast<const float4*>(&As[kk][trow * 8 + 4]);
            *reinterpret_cast<float4*>(&b[0]) = *reinterpret_cast<const float4*>(&Bs[kk][tcol * 8]);
            *reinterpret_cast<float4*>(&b[4]) = *reinterpret_cast<const float4*>(&Bs[kk][tcol * 8 + 4]);
            #pragma unroll
            for (int i = 0; i < 8; ++i)
                #pragma unroll
                for (int j = 0; j < 8; ++j)
                    acc[i][j] += a[i] * b[j];
        }
        __syncthreads();
    }
    #pragma unroll
    for (int i = 0; i < 8; ++i) {
        const int m = m0 + trow * 8 + i;
        #pragma unroll
        for (int j = 0; j < 8; j += 4) {
            const int n = n0 + tcol * 8 + j;
            float4 bv = *reinterpret_cast<const float4*>(&bias[n]);
            float4 o;
            o.x = acc[i][j + 0] + bv.x;
            o.y = acc[i][j + 1] + bv.y;
            o.z = acc[i][j + 2] + bv.z;
            o.w = acc[i][j + 3] + bv.w;
            *reinterpret_cast<float4*>(&C[(size_t)m * N + n]) = o;
        }
    }
}

// ---------------- QK^T * scale + relative-position bias ----------------
// grid: (16 ktile, 16 qtile, 256 batch=b*H+h); 64x64 out tile, K-dim=64 full
__global__ void __launch_bounds__(256)
qk_kernel(const float* __restrict__ biases, const int* __restrict__ bidx) {
    const int bz = blockIdx.z;
    const int b = bz >> 3, h = bz & 7;
    const int q0 = blockIdx.y * 64;
    const int k0 = blockIdx.x * 64;
    __shared__ float Qs[64][65];   // [d][q]
    __shared__ float Ks[64][65];   // [d][k]
    const int tid = threadIdx.x;
    const size_t tokbase = (size_t)b * NN;
    #pragma unroll
    for (int i = 0; i < 4; ++i) {
        int idx = tid + i * 256;        // 0..1023
        int row = idx >> 4;
        int c4 = idx & 15;
        float4 qv = *reinterpret_cast<const float4*>(
            &g_qkv[(tokbase + q0 + row) * QKVV + h * 384 + c4 * 4]);
        Qs[c4 * 4 + 0][row] = qv.x; Qs[c4 * 4 + 1][row] = qv.y;
        Qs[c4 * 4 + 2][row] = qv.z; Qs[c4 * 4 + 3][row] = qv.w;
        float4 kv = *reinterpret_cast<const float4*>(
            &g_qkv[(tokbase + k0 + row) * QKVV + h * 384 + 64 + c4 * 4]);
        Ks[c4 * 4 + 0][row] = kv.x; Ks[c4 * 4 + 1][row] = kv.y;
        Ks[c4 * 4 + 2][row] = kv.z; Ks[c4 * 4 + 3][row] = kv.w;
    }
    __syncthreads();
    const int tcol = tid & 15, trow = tid >> 4;
    float acc[4][4] = {};
    #pragma unroll 16
    for (int d = 0; d < 64; ++d) {
        float a[4], bb[4];
        #pragma unroll
        for (int i = 0; i < 4; ++i) a[i] = Qs[d][trow * 4 + i];
        #pragma unroll
        for (int j = 0; j < 4; ++j) bb[j] = Ks[d][tcol * 4 + j];
        #pragma unroll
        for (int i = 0; i < 4; ++i)
            #pragma unroll
            for (int j = 0; j < 4; ++j)
                acc[i][j] += a[i] * bb[j];
    }
    #pragma unroll
    for (int i = 0; i < 4; ++i) {
        const int q = q0 + trow * 4 + i;
        const int* brow = &bidx[(size_t)q * NN + k0 + tcol * 4];
        float* orow = &g_attn[((size_t)bz * NN + q) * NN + k0 + tcol * 4];
        #pragma unroll
        for (int j = 0; j < 4; ++j) {
            float bias = biases[h * 1024 + brow[j]];
            orow[j] = acc[i][j] * SCALE + bias;
        }
    }
}

// ---------------- softmax over k (in-place on g_attn) ----------------
__global__ void __launch_bounds__(256)
softmax_kernel() {
    const size_t base = (size_t)blockIdx.x * NN;
    float4* p = reinterpret_cast<float4*>(g_attn + base);
    const int t = threadIdx.x;
    const int w = t >> 5, l = t & 31;
    __shared__ float red[8];
    float4 v = p[t];
    float m = fmaxf(fmaxf(v.x, v.y), fmaxf(v.z, v.w));
    #pragma unroll
    for (int o = 16; o > 0; o >>= 1) m = fmaxf(m, __shfl_xor_sync(0xffffffffu, m, o));
    if (l == 0) red[w] = m;
    __syncthreads();
    if (t == 0) {
        float mm = red[0];
        #pragma unroll
        for (int i = 1; i < 8; ++i) mm = fmaxf(mm, red[i]);
        red[0] = mm;
    }
    __syncthreads();
    m = red[0];
    float4 e;
    e.x = __expf(v.x - m); e.y = __expf(v.y - m);
    e.z = __expf(v.z - m); e.w = __expf(v.w - m);
    float s = e.x + e.y + e.z + e.w;
    #pragma unroll
    for (int o = 16; o > 0; o >>= 1) s += __shfl_xor_sync(0xffffffffu, s, o);
    __syncthreads();                 // everyone has read red[0] before reuse
    if (l == 0) red[w] = s;
    __syncthreads();
    if (t == 0) {
        float tot = 0.f;
        #pragma unroll
        for (int i = 0; i < 8; ++i) tot += red[i];
        red[0] = tot;
    }
    __syncthreads();
    const float inv = 1.0f / red[0];
    e.x *= inv; e.y *= inv; e.z *= inv; e.w *= inv;
    p[t] = e;
}

// ---------------- attn @ V  -> g_av[b, q, h*256 + d] ----------------
// grid: (4 dtile, 8 qtile, 256 batch); BM=128, BN=64, BK=16, TM=8, TN=4
__global__ void __launch_bounds__(256)
av_kernel() {
    const int bz = blockIdx.z;
    const int b = bz >> 3, h = bz & 7;
    const int m0 = blockIdx.y * 128;
    const int n0 = blockIdx.x * 64;
    __shared__ float As[16][128];
    __shared__ float Bs[16][64];
    const int tid = threadIdx.x;
    const int tcol = tid & 15, trow = tid >> 4;
    float acc[8][4] = {};
    const float* Abase = g_attn + (size_t)bz * NN * NN;
    const size_t vbase = (size_t)b * NN * QKVV + h * 384 + 128 + n0;
    for (int kt = 0; kt < NN; kt += 16) {
        #pragma unroll
        for (int i = 0; i < 2; ++i) {
            int idx = tid + i * 256;
            int m = idx >> 2;
            int c = idx & 3;
            float4 v = *reinterpret_cast<const float4*>(
                &Abase[(size_t)(m0 + m) * NN + kt + c * 4]);
            As[c * 4 + 0][m] = v.x; As[c * 4 + 1][m] = v.y;
            As[c * 4 + 2][m] = v.z; As[c * 4 + 3][m] = v.w;
        }
        {
            int r = tid >> 4;
            int c = tid & 15;
            *reinterpret_cast<float4*>(&Bs[r][c * 4]) =
                *reinterpret_cast<const float4*>(
                    &g_qkv[vbase + (size_t)(kt + r) * QKVV + c * 4]);
        }
        __syncthreads();
        #pragma unroll
        for (int kk = 0; kk < 16; ++kk) {
            float a[8], bb[4];
            *reinterpret_cast<float4*>(&a[0]) = *reinterpret_cast<const float4*>(&As[kk][trow * 8]);
            *reinterpret_cast<float4*>(&a[4]) = *reinterpret_cast<const float4*>(&As[kk][trow * 8 + 4]);
            *reinterpret_cast<float4*>(&bb[0]) = *reinterpret_cast<const float4*>(&Bs[kk][tcol * 4]);
            #pragma unroll
            for (int i = 0; i < 8; ++i)
                #pragma unroll
                for (int j = 0; j < 4; ++j)
                    acc[i][j] += a[i] * bb[j];
        }
        __syncthreads();
    }
    #pragma unroll
    for (int i = 0; i < 8; ++i) {
        const int q = m0 + trow * 8 + i;
        float4 o;
        o.x = acc[i][0]; o.y = acc[i][1]; o.z = acc[i][2]; o.w = acc[i][3];
        *reinterpret_cast<float4*>(
            &g_av[((size_t)b * NN + q) * DHV + h * DV + n0 + tcol * 4]) = o;
    }
}

// ---------------- launch ----------------
extern "C" void kernel_launch(void* const* d_in, const int* in_sizes, int n_in,
                              void* d_out, int out_size) {
    (void)in_sizes; (void)n_in; (void)out_size;
    const float* x      = (const float*)d_in[0];
    const float* gamma  = (const float*)d_in[1];
    const float* beta   = (const float*)d_in[2];
    const float* qkv_w  = (const float*)d_in[3];
    const float* qkv_b  = (const float*)d_in[4];
    const float* proj_w = (const float*)d_in[5];
    const float* proj_b = (const float*)d_in[6];
    const float* biases = (const float*)d_in[7];
    const int*   bidx   = (const int*)d_in[8];
    float* out = (float*)d_out;

    float *xn_p = nullptr, *qkv_p = nullptr, *av_p = nullptr;
    cudaGetSymbolAddress((void**)&xn_p, g_xn);
    cudaGetSymbolAddress((void**)&qkv_p, g_qkv);
    cudaGetSymbolAddress((void**)&av_p, g_av);

    ln_kernel<<<BB * NN, 128>>>(x, gamma, beta);

    dim3 g1(QKVV / 128, (BB * NN) / 128);           // (24, 256)
    sgemm_bias<<<g1, 256>>>(xn_p, qkv_w, qkv_b, qkv_p, BB * NN, QKVV, DIMV);

    dim3 g2(NN / 64, NN / 64, BB * HH);             // (16, 16, 256)
    qk_kernel<<<g2, 256>>>(biases, bidx);

    softmax_kernel<<<BB * HH * NN, 256>>>();        // 262144 rows

    dim3 g3(DV / 64, NN / 128, BB * HH);            // (4, 8, 256)
    av_kernel<<<g3, 256>>>();

    dim3 g4(DIMV / 128, (BB * NN) / 128);           // (4, 256)
    sgemm_bias<<<g4, 256>>>(av_p, proj_w, proj_b, out, BB * NN, DIMV, DHV);
}

// round 2
// speedup vs baseline: 2.6922x; 2.6922x over previous
#include <cuda_runtime.h>
#include <cstdint>
#include <cstddef>

#define BB   32
#define NN   1024
#define DIMV 512
#define HH   8
#define KDV  64
#define DV   256
#define DHV  2048
#define QKVV 3072

// ---------------- scratch (device globals; allocation-free) ----------------
__device__ float g_xn[(size_t)BB * NN * DIMV];        //  64 MB
__device__ float g_qkv[(size_t)BB * NN * QKVV];       // 384 MB
__device__ float g_attn[(size_t)BB * HH * NN * NN];   //   1 GB (bz, q, k)
__device__ float g_av[(size_t)BB * NN * DHV];         // 256 MB (b, q, h, d)
__device__ float g_biasmat[(size_t)HH * NN * NN];     //  32 MB (h, q, k)

// ---------------- helpers ----------------
__device__ __forceinline__ uint32_t f2tf32(float x) {
    uint32_t r;
    asm("cvt.rna.tf32.f32 %0, %1;" : "=r"(r) : "f"(x));
    return r;
}

__device__ __forceinline__ void mma_tf32(float c[4], const uint32_t a[4],
                                         const uint32_t b[2]) {
    asm volatile(
        "mma.sync.aligned.m16n8k8.row.col.f32.tf32.tf32.f32 "
        "{%0,%1,%2,%3}, {%4,%5,%6,%7}, {%8,%9}, {%0,%1,%2,%3};\n"
        : "+f"(c[0]), "+f"(c[1]), "+f"(c[2]), "+f"(c[3])
        : "r"(a[0]), "r"(a[1]), "r"(a[2]), "r"(a[3]), "r"(b[0]), "r"(b[1]));
}

// ---------------- LayerNorm: one block per token row ----------------
__global__ void __launch_bounds__(128)
ln_kernel(const float* __restrict__ x, const float* __restrict__ gamma,
          const float* __restrict__ beta) {
    const int row = blockIdx.x;
    const int t = threadIdx.x;
    const float4 v = reinterpret_cast<const float4*>(x)[(size_t)row * (DIMV / 4) + t];
    float s  = v.x + v.y + v.z + v.w;
    float sq = v.x * v.x + v.y * v.y + v.z * v.z + v.w * v.w;
    #pragma unroll
    for (int o = 16; o > 0; o >>= 1) {
        s  += __shfl_xor_sync(0xffffffffu, s, o);
        sq += __shfl_xor_sync(0xffffffffu, sq, o);
    }
    __shared__ float ss[4], ssq[4];
    const int w = t >> 5, l = t & 31;
    if (l == 0) { ss[w] = s; ssq[w] = sq; }
    __syncthreads();
    if (t == 0) {
        float S  = ss[0] + ss[1] + ss[2] + ss[3];
        float SQ = ssq[0] + ssq[1] + ssq[2] + ssq[3];
        float mu = S * (1.0f / DIMV);
        float var = SQ * (1.0f / DIMV) - mu * mu;
        ss[0]  = mu;
        ssq[0] = rsqrtf(var + 1e-5f);
    }
    __syncthreads();
    const float mu = ss[0], rstd = ssq[0];
    const float4 g  = reinterpret_cast<const float4*>(gamma)[t];
    const float4 bt = reinterpret_cast<const float4*>(beta)[t];
    float4 o;
    o.x = (v.x - mu) * rstd * g.x + bt.x;
    o.y = (v.y - mu) * rstd * g.y + bt.y;
    o.z = (v.z - mu) * rstd * g.z + bt.z;
    o.w = (v.w - mu) * rstd * g.w + bt.w;
    reinterpret_cast<float4*>(g_xn)[(size_t)row * (DIMV / 4) + t] = o;
}

// ---------------- dense bias matrix: g_biasmat[h][q][k] ----------------
__global__ void __launch_bounds__(256)
biasmat_kernel(const float* __restrict__ biases, const int* __restrict__ bidx) {
    const int h = blockIdx.y;
    const size_t i = (size_t)blockIdx.x * 256 + threadIdx.x;   // 0..1M-1
    g_biasmat[(size_t)h * NN * NN + i] = biases[h * 1024 + bidx[i]];
}

// ---------------- unified tf32 tensor-core GEMM ----------------
// Tile: BM=128, BN=128, BK=32; 256 threads = 8 warps (4 along M x 2 along N);
// warp tile 32x64 = 2 x 8 mma(m16n8k8) per k-step; 4 k-steps per BK.
// MODE 0: g_xn @ qkv_w + qkv_b -> g_qkv
// MODE 1: per bz=(b,h): Q @ K^T * SCALE + biasmat -> g_attn
// MODE 2: per bz=(b,h): attn @ V -> g_av
// MODE 3: g_av @ proj_w + proj_b -> out
template<int MODE>
__global__ void __launch_bounds__(256, 2)
mm_tf32(const float* __restrict__ Barg, float* __restrict__ Carg,
        const float* __restrict__ biasv) {
    // compile-time shape config
    constexpr int  LDA    = (MODE == 0) ? DIMV : (MODE == 1) ? QKVV
                          : (MODE == 2) ? NN   : DHV;
    constexpr int  LDB    = (MODE == 0) ? QKVV : (MODE == 1) ? QKVV
                          : (MODE == 2) ? QKVV : DIMV;
    constexpr int  LDC    = (MODE == 0) ? QKVV : (MODE == 1) ? NN
                          : (MODE == 2) ? DHV  : DIMV;
    constexpr int  KDIM   = (MODE == 0) ? DIMV : (MODE == 1) ? KDV
                          : (MODE == 2) ? NN   : DHV;
    constexpr bool TRANSB = (MODE == 1);

    __shared__ uint32_t As[128][36];
    __shared__ uint32_t Bs[32][136];

    const int tid = threadIdx.x;
    const int m0 = blockIdx.y * 128;
    const int n0 = blockIdx.x * 128;

    // resolve per-mode base pointers
    const float* Ap;
    const float* Bp;
    float* Cp;
    const float* bmp = nullptr;
    if (MODE == 0) {
        Ap = g_xn; Bp = Barg; Cp = g_qkv;
    } else if (MODE == 1) {
        const int bz = blockIdx.z, b = bz >> 3, h = bz & 7;
        Ap = g_qkv + (size_t)b * NN * QKVV + h * 384;
        Bp = g_qkv + (size_t)b * NN * QKVV + h * 384 + 64;
        Cp = g_attn + (size_t)bz * NN * NN;
        bmp = g_biasmat + (size_t)h * NN * NN;
    } else if (MODE == 2) {
        const int bz = blockIdx.z, b = bz >> 3, h = bz & 7;
        Ap = g_attn + (size_t)bz * NN * NN;
        Bp = g_qkv + (size_t)b * NN * QKVV + h * 384 + 128;
        Cp = g_av + (size_t)b * NN * DHV + h * DV;
    } else {
        Ap = g_av; Bp = Barg; Cp = Carg;
    }

    const int wid = tid >> 5, lane = tid & 31;
    const int wm = wid >> 1, wn = wid & 1;
    const int grp = lane >> 2, qd = lane & 3;

    float acc[2][8][4] = {};

    for (int kt = 0; kt < KDIM; kt += 32) {
        // --- stage A tile (BM x BK), converting to tf32 ---
        {
            const int r = tid >> 3, c4 = (tid & 7) * 4;
            #pragma unroll
            for (int i = 0; i < 4; ++i) {
                const int rr = r + i * 32;
                const float4 v = *reinterpret_cast<const float4*>(
                    &Ap[(size_t)(m0 + rr) * LDA + kt + c4]);
                As[rr][c4 + 0] = f2tf32(v.x);
                As[rr][c4 + 1] = f2tf32(v.y);
                As[rr][c4 + 2] = f2tf32(v.z);
                As[rr][c4 + 3] = f2tf32(v.w);
            }
        }
        // --- stage B tile (BK x BN) ---
        if (!TRANSB) {
            const int r = tid >> 5, c4 = (tid & 31) * 4;
            #pragma unroll
            for (int i = 0; i < 4; ++i) {
                const int rr = r + i * 8;
                const float4 v = *reinterpret_cast<const float4*>(
                    &Bp[(size_t)(kt + rr) * LDB + n0 + c4]);
                Bs[rr][c4 + 0] = f2tf32(v.x);
                Bs[rr][c4 + 1] = f2tf32(v.y);
                Bs[rr][c4 + 2] = f2tf32(v.z);
                Bs[rr][c4 + 3] = f2tf32(v.w);
            }
        } else {
            const int nr = tid >> 3, c4 = (tid & 7) * 4;
            #pragma unroll
            for (int i = 0; i < 4; ++i) {
                const int nn = nr + i * 32;
                const float4 v = *reinterpret_cast<const float4*>(
                    &Bp[(size_t)(n0 + nn) * LDB + kt + c4]);
                Bs[c4 + 0][nn] = f2tf32(v.x);
                Bs[c4 + 1][nn] = f2tf32(v.y);
                Bs[c4 + 2][nn] = f2tf32(v.z);
                Bs[c4 + 3][nn] = f2tf32(v.w);
            }
        }
        __syncthreads();

        #pragma unroll
        for (int ks = 0; ks < 4; ++ks) {
            uint32_t af[2][4];
            #pragma unroll
            for (int mt = 0; mt < 2; ++mt) {
                const int mr = wm * 32 + mt * 16 + grp;
                const int kc = ks * 8 + qd;
                af[mt][0] = As[mr][kc];
                af[mt][1] = As[mr + 8][kc];
                af[mt][2] = As[mr][kc + 4];
                af[mt][3] = As[mr + 8][kc + 4];
            }
            uint32_t bf[8][2];
            #pragma unroll
            for (int nt = 0; nt < 8; ++nt) {
                const int nc = wn * 64 + nt * 8 + grp;
                bf[nt][0] = Bs[ks * 8 + qd][nc];
                bf[nt][1] = Bs[ks * 8 + qd + 4][nc];
            }
            #pragma unroll
            for (int mt = 0; mt < 2; ++mt)
                #pragma unroll
                for (int nt = 0; nt < 8; ++nt)
                    mma_tf32(acc[mt][nt], af[mt], bf[nt]);
        }
        __syncthreads();
    }

    // --- epilogue ---
    #pragma unroll
    for (int mt = 0; mt < 2; ++mt) {
        #pragma unroll
        for (int nt = 0; nt < 8; ++nt) {
            const int r0 = m0 + wm * 32 + mt * 16 + grp;
            const int c0 = n0 + wn * 64 + nt * 8 + 2 * qd;
            float v0 = acc[mt][nt][0], v1 = acc[mt][nt][1];
            float v2 = acc[mt][nt][2], v3 = acc[mt][nt][3];
            if (MODE == 0 || MODE == 3) {
                const float b0 = biasv[c0], b1 = biasv[c0 + 1];
                v0 += b0; v1 += b1; v2 += b0; v3 += b1;
            } else if (MODE == 1) {
                const float2 bm0 = *reinterpret_cast<const float2*>(
                    &bmp[(size_t)r0 * NN + c0]);
                const float2 bm1 = *reinterpret_cast<const float2*>(
                    &bmp[(size_t)(r0 + 8) * NN + c0]);
                v0 = v0 * 0.125f + bm0.x; v1 = v1 * 0.125f + bm0.y;
                v2 = v2 * 0.125f + bm1.x; v3 = v3 * 0.125f + bm1.y;
            }
            *reinterpret_cast<float2*>(&Cp[(size_t)r0 * LDC + c0]) =
                make_float2(v0, v1);
            *reinterpret_cast<float2*>(&Cp[(size_t)(r0 + 8) * LDC + c0]) =
                make_float2(v2, v3);
        }
    }
}

// ---------------- softmax over k (in-place on g_attn) ----------------
__global__ void __launch_bounds__(256)
softmax_kernel() {
    const size_t base = (size_t)blockIdx.x * NN;
    float4* p = reinterpret_cast<float4*>(g_attn + base);
    const int t = threadIdx.x;
    const int w = t >> 5, l = t & 31;
    __shared__ float red[8];
    float4 v = p[t];
    float m = fmaxf(fmaxf(v.x, v.y), fmaxf(v.z, v.w));
    #pragma unroll
    for (int o = 16; o > 0; o >>= 1) m = fmaxf(m, __shfl_xor_sync(0xffffffffu, m, o));
    if (l == 0) red[w] = m;
    __syncthreads();
    if (t == 0) {
        float mm = red[0];
        #pragma unroll
        for (int i = 1; i < 8; ++i) mm = fmaxf(mm, red[i]);
        red[0] = mm;
    }
    __syncthreads();
    m = red[0];
    float4 e;
    e.x = __expf(v.x - m); e.y = __expf(v.y - m);
    e.z = __expf(v.z - m); e.w = __expf(v.w - m);
    float s = e.x + e.y + e.z + e.w;
    #pragma unroll
    for (int o = 16; o > 0; o >>= 1) s += __shfl_xor_sync(0xffffffffu, s, o);
    __syncthreads();
    if (l == 0) red[w] = s;
    __syncthreads();
    if (t == 0) {
        float tot = 0.f;
        #pragma unroll
        for (int i = 0; i < 8; ++i) tot += red[i];
        red[0] = tot;
    }
    __syncthreads();
    const float inv = 1.0f / red[0];
    e.x *= inv; e.y *= inv; e.z *= inv; e.w *= inv;
    p[t] = e;
}

// ---------------- launch ----------------
extern "C" void kernel_launch(void* const* d_in, const int* in_sizes, int n_in,
                              void* d_out, int out_size) {
    (void)in_sizes; (void)n_in; (void)out_size;
    const float* x      = (const float*)d_in[0];
    const float* gamma  = (const float*)d_in[1];
    const float* beta   = (const float*)d_in[2];
    const float* qkv_w  = (const float*)d_in[3];
    const float* qkv_b  = (const float*)d_in[4];
    const float* proj_w = (const float*)d_in[5];
    const float* proj_b = (const float*)d_in[6];
    const float* biases = (const float*)d_in[7];
    const int*   bidx   = (const int*)d_in[8];
    float* out = (float*)d_out;

    ln_kernel<<<BB * NN, 128>>>(x, gamma, beta);

    biasmat_kernel<<<dim3(NN * NN / 256, HH), 256>>>(biases, bidx);

    // QKV: [32768 x 512] @ [512 x 3072]
    mm_tf32<0><<<dim3(QKVV / 128, (BB * NN) / 128), 256>>>(qkv_w, nullptr, qkv_b);

    // QK^T per (b,h): [1024 x 64] @ [64 x 1024] * scale + bias
    mm_tf32<1><<<dim3(NN / 128, NN / 128, BB * HH), 256>>>(nullptr, nullptr, nullptr);

    softmax_kernel<<<BB * HH * NN, 256>>>();

    // attn @ V per (b,h): [1024 x 1024] @ [1024 x 256]
    mm_tf32<2><<<dim3(DV / 128, NN / 128, BB * HH), 256>>>(nullptr, nullptr, nullptr);

    // proj: [32768 x 2048] @ [2048 x 512]
    mm_tf32<3><<<dim3(DIMV / 128, (BB * NN) / 128), 256>>>(proj_w, out, proj_b);
}